// round 1
// baseline (speedup 1.0000x reference)
#include <cuda_runtime.h>
#include <math.h>

// ---------------- problem constants ----------------
#define BSZ 32
#define PP 196          // 14*14 pixels
#define ENCD 2048
#define ATTD 512
#define DECD 512
#define EMBD 512
#define VV 10000
#define LL 52
#define TT 51           // decode steps
#define XKD 2560        // EMB + ENC (LSTM input width)

// output layout (floats), concat of (pred, toks, dlen, alphas, sort)
#define OFF_PRED  0L
#define OFF_TOKS  ((long)BSZ*TT*VV)                 // 16,320,000
#define OFF_DLEN  (OFF_TOKS + (long)BSZ*LL)         // +1664
#define OFF_ALPHA (OFF_DLEN + (long)BSZ)            // +32
#define OFF_SORT  (OFF_ALPHA + (long)BSZ*TT*PP)     // +319,872

// ---------------- device scratch (static, allocation-free) ----------------
__device__ float g_enc[BSZ*PP*ATTD];        // 12.8 MB: enc_att (sorted order)
__device__ float g_part[16L*BSZ*10016];     // split-K partials, up to 16 slices
__device__ float g_mean[BSZ*ENCD];
__device__ float g_h[BSZ*DECD];
__device__ float g_c[BSZ*DECD];
__device__ float g_hn[BSZ*DECD];
__device__ float g_dec[BSZ*ATTD];
__device__ float g_awe[BSZ*ENCD];
__device__ float g_x[BSZ*XKD];              // [emb(512) ; gated awe(2048)]
__device__ float g_gates[BSZ*2048];
__device__ float g_alpha[BSZ*PP];
__device__ float g_bcomb[2048];             // b_ih + b_hh
__device__ int   g_sort[BSZ];
__device__ int   g_dlen[BSZ];
__device__ int   g_toks[BSZ*LL];

__device__ __forceinline__ float sigm(float x) { return 1.f / (1.f + expf(-x)); }

// ---------------- sort (stable argsort descending) + gathers ----------------
__global__ void k_sort(const int* __restrict__ lens, const int* __restrict__ toks,
                       float* __restrict__ out) {
    int tid = threadIdx.x;
    if (tid < BSZ) {
        int li = lens[tid];
        int r = 0;
        for (int j = 0; j < BSZ; j++) {
            int lj = lens[j];
            if (lj > li || (lj == li && j < tid)) r++;
        }
        g_sort[r] = tid;
    }
    __syncthreads();
    if (tid < BSZ) {
        int si = g_sort[tid];
        int dl = lens[si] - 1;
        g_dlen[tid] = dl;
        out[OFF_DLEN + tid] = (float)dl;
        out[OFF_SORT + tid] = (float)si;
    }
    __syncthreads();
    for (int idx = tid; idx < BSZ*LL; idx += blockDim.x) {
        int b = idx / LL, l = idx - b*LL;
        int tk = toks[g_sort[b]*LL + l];
        g_toks[idx] = tk;
        out[OFF_TOKS + idx] = (float)tk;
    }
}

// ---------------- mean image feature (sorted) ----------------
__global__ void k_mean(const float* __restrict__ img) {
    int b = blockIdx.x;
    long base = (long)g_sort[b] * PP * ENCD;
    for (int e = threadIdx.x; e < ENCD; e += blockDim.x) {
        float s = 0.f;
        const float* p = img + base + e;
        #pragma unroll 4
        for (int pp = 0; pp < PP; pp++) s += p[(long)pp * ENCD];
        g_mean[b*ENCD + e] = s * (1.f / (float)PP);
    }
}

// ---------------- combined LSTM bias ----------------
__global__ void k_bcomb(const float* __restrict__ bih, const float* __restrict__ bhh) {
    int i = blockIdx.x * 256 + threadIdx.x;
    if (i < 2048) g_bcomb[i] = bih[i] + bhh[i];
}

// ---------------- enc_att = img_sorted @ W_enc^T + b_enc ----------------
// C[6272,512], K=2048.  BM=128, BN=128, BK=16, 256 threads, TM=TN=8.
__global__ void k_encatt(const float* __restrict__ img, const float* __restrict__ W,
                         const float* __restrict__ bias) {
    __shared__ float As[16*132];
    __shared__ float Bs[16*132];
    __shared__ long  rowbase[128];
    int tid = threadIdx.x;
    int bx = blockIdx.x;        // n tile (0..3)
    int by = blockIdx.y;        // m tile (0..48)

    if (tid < 128) {
        int rr = by*128 + tid;
        int b = rr / PP, p = rr - b*PP;
        rowbase[tid] = ((long)g_sort[b]*PP + p) * ENCD;
    }
    __syncthreads();

    float acc[8][8];
    #pragma unroll
    for (int i = 0; i < 8; i++)
        #pragma unroll
        for (int j = 0; j < 8; j++) acc[i][j] = 0.f;

    int tx = tid & 15, ty = tid >> 4;
    int m0 = ty*8, n0 = tx*8;

    for (int k0 = 0; k0 < ENCD; k0 += 16) {
        // stage A (128x16) and B (128x16)
        #pragma unroll
        for (int i = 0; i < 8; i++) {
            int idx = i*256 + tid;
            int k = idx & 15, r = idx >> 4;
            As[k*132 + r] = img[rowbase[r] + k0 + k];
            Bs[k*132 + r] = W[(long)(bx*128 + r)*ENCD + k0 + k];
        }
        __syncthreads();
        #pragma unroll 4
        for (int k = 0; k < 16; k++) {
            float a[8], bb[8];
            float4 a0 = *(const float4*)&As[k*132 + m0];
            float4 a1 = *(const float4*)&As[k*132 + m0 + 4];
            float4 b0 = *(const float4*)&Bs[k*132 + n0];
            float4 b1 = *(const float4*)&Bs[k*132 + n0 + 4];
            a[0]=a0.x;a[1]=a0.y;a[2]=a0.z;a[3]=a0.w;a[4]=a1.x;a[5]=a1.y;a[6]=a1.z;a[7]=a1.w;
            bb[0]=b0.x;bb[1]=b0.y;bb[2]=b0.z;bb[3]=b0.w;bb[4]=b1.x;bb[5]=b1.y;bb[6]=b1.z;bb[7]=b1.w;
            #pragma unroll
            for (int i = 0; i < 8; i++)
                #pragma unroll
                for (int j = 0; j < 8; j++)
                    acc[i][j] = fmaf(a[i], bb[j], acc[i][j]);
        }
        __syncthreads();
    }
    #pragma unroll
    for (int i = 0; i < 8; i++) {
        int row = by*128 + m0 + i;
        #pragma unroll
        for (int j = 0; j < 8; j++) {
            int col = bx*128 + n0 + j;
            g_enc[(long)row*ATTD + col] = acc[i][j] + bias[col];
        }
    }
}

// ---------------- skinny GEMM partial: part[s] = X[32,Kslice] @ W[N,Kslice]^T --------
// grid (ceil(N/128), SK), 256 threads, TM=4 TN=4.
__global__ void k_gpart(const float* __restrict__ X, const float* __restrict__ W,
                        int N, int K, int kslice, int s_off) {
    __shared__ float Xs[32*36];
    __shared__ float Ws[32*132];
    int tid = threadIdx.x;
    int nblk = blockIdx.x;
    int s = s_off + blockIdx.y;
    int k0 = blockIdx.y * kslice;

    float acc[4][4];
    #pragma unroll
    for (int i = 0; i < 4; i++)
        #pragma unroll
        for (int j = 0; j < 4; j++) acc[i][j] = 0.f;

    int m0 = (tid >> 5) * 4;      // 0..28
    int n0 = (tid & 31) * 4;      // 0..124

    for (int kk = 0; kk < kslice; kk += 32) {
        int kc = k0 + kk;
        // stage X chunk 32x32 transposed
        #pragma unroll
        for (int i = 0; i < 4; i++) {
            int idx = i*256 + tid;
            int k = idx & 31, m = idx >> 5;
            Xs[k*36 + m] = X[(long)m*K + kc + k];
        }
        // stage W chunk 128x32 transposed
        #pragma unroll
        for (int i = 0; i < 16; i++) {
            int idx = i*256 + tid;
            int k = idx & 31, n = idx >> 5;
            int ng = nblk*128 + n;
            Ws[k*132 + n] = (ng < N) ? W[(long)ng*K + kc + k] : 0.f;
        }
        __syncthreads();
        #pragma unroll 8
        for (int k = 0; k < 32; k++) {
            float4 xa = *(const float4*)&Xs[k*36 + m0];
            float4 wb = *(const float4*)&Ws[k*132 + n0];
            float xv[4] = {xa.x, xa.y, xa.z, xa.w};
            float wv[4] = {wb.x, wb.y, wb.z, wb.w};
            #pragma unroll
            for (int i = 0; i < 4; i++)
                #pragma unroll
                for (int j = 0; j < 4; j++)
                    acc[i][j] = fmaf(xv[i], wv[j], acc[i][j]);
        }
        __syncthreads();
    }
    #pragma unroll
    for (int i = 0; i < 4; i++) {
        int m = m0 + i;
        #pragma unroll
        for (int j = 0; j < 4; j++) {
            int ng = nblk*128 + n0 + j;
            if (ng < N) g_part[((long)s*BSZ + m)*N + ng] = acc[i][j];
        }
    }
}

// ---------------- reduce partials + epilogue ----------------
// mode 0: out[m*ostride+n] = sum + bias[n]
// mode 2: out[m*ostride+n] = aux[m*N+n] * sigmoid(sum + bias[n])    (beta gate)
// mode 3: out[m*ostride+n] = (t < dlen[m]) ? sum + bias[n] : 0      (FC preds)
__global__ void k_reduce(int N, int S, const float* __restrict__ bias,
                         float* __restrict__ out, long ostride, int mode,
                         const float* __restrict__ aux, int t) {
    int idx = blockIdx.x*256 + threadIdx.x;
    if (idx >= BSZ*N) return;
    int m = idx / N, n = idx - m*N;
    const float* p = g_part + (long)m*N + n;
    float s = 0.f;
    for (int si = 0; si < S; si++) s += p[(long)si*BSZ*N];
    s += bias[n];
    if (mode == 0) {
        out[(long)m*ostride + n] = s;
    } else if (mode == 2) {
        out[(long)m*ostride + n] = aux[m*N + n] * sigm(s);
    } else {
        out[(long)m*ostride + n] = (t < g_dlen[m]) ? s : 0.f;
    }
}

// ---------------- attention: scores + softmax + alpha out + emb copy ----------------
__global__ void k_attn(const float* __restrict__ emb_table, const float* __restrict__ w_full,
                       const float* __restrict__ b_full, float* __restrict__ out, int t) {
    __shared__ float dec_s[ATTD];
    __shared__ float wf[ATTD];
    __shared__ float sc[PP];
    __shared__ float red[256];
    int b = blockIdx.x;
    int tid = threadIdx.x;
    bool act = (t < g_dlen[b]);

    // copy embedding of current token into LSTM input buffer
    int tok = g_toks[b*LL + t];
    for (int e = tid; e < EMBD; e += 256)
        g_x[(long)b*XKD + e] = emb_table[(long)tok*EMBD + e];
    for (int a = tid; a < ATTD; a += 256) {
        dec_s[a] = g_dec[b*ATTD + a];
        wf[a] = w_full[a];
    }
    __syncthreads();

    // scores over 196 pixels
    int wid = tid >> 5, lane = tid & 31;
    float bf = b_full[0];
    for (int p = wid; p < PP; p += 8) {
        const float* er = g_enc + ((long)b*PP + p)*ATTD;
        float s = 0.f;
        #pragma unroll 4
        for (int a = lane; a < ATTD; a += 32) {
            float v = er[a] + dec_s[a];
            s = fmaf(fmaxf(v, 0.f), wf[a], s);
        }
        #pragma unroll
        for (int off = 16; off > 0; off >>= 1)
            s += __shfl_xor_sync(0xffffffffu, s, off);
        if (lane == 0) sc[p] = s + bf;
    }
    __syncthreads();

    // softmax over PP
    float v = (tid < PP) ? sc[tid] : -3.0e38f;
    red[tid] = v; __syncthreads();
    for (int s2 = 128; s2 > 0; s2 >>= 1) {
        if (tid < s2) red[tid] = fmaxf(red[tid], red[tid + s2]);
        __syncthreads();
    }
    float mx = red[0];
    __syncthreads();
    float ev = (tid < PP) ? expf(sc[tid] - mx) : 0.f;
    red[tid] = ev; __syncthreads();
    for (int s2 = 128; s2 > 0; s2 >>= 1) {
        if (tid < s2) red[tid] += red[tid + s2];
        __syncthreads();
    }
    float inv = 1.f / red[0];
    if (tid < PP) {
        float al = ev * inv;
        g_alpha[b*PP + tid] = al;
        out[OFF_ALPHA + ((long)b*TT + t)*PP + tid] = act ? al : 0.f;
    }
}

// ---------------- awe = alpha @ img_sorted  (grid 32 b x 8 e-chunks) ----------------
__global__ void k_awe(const float* __restrict__ img) {
    __shared__ float al[PP];
    int b = blockIdx.x >> 3;
    int ch = blockIdx.x & 7;
    int tid = threadIdx.x;
    if (tid < PP) al[tid] = g_alpha[b*PP + tid];
    __syncthreads();
    int e = ch*256 + tid;
    const float* base = img + ((long)g_sort[b]*PP)*ENCD + e;
    float s = 0.f;
    #pragma unroll 4
    for (int p = 0; p < PP; p++) s = fmaf(al[p], base[(long)p*ENCD], s);
    g_awe[b*ENCD + e] = s;
}

// ---------------- LSTM pointwise update ----------------
__global__ void k_lstm(int t) {
    int idx = blockIdx.x*256 + threadIdx.x;
    if (idx >= BSZ*DECD) return;
    int m = idx / DECD, j = idx - m*DECD;
    const float* g = g_gates + m*2048;
    float gi = g[j], gf = g[j + 512], gg = g[j + 1024], go = g[j + 1536];
    float c = g_c[idx];
    float cn = sigm(gf)*c + sigm(gi)*tanhf(gg);
    float hn = sigm(go)*tanhf(cn);
    g_hn[idx] = hn;
    if (t < g_dlen[m]) { g_c[idx] = cn; g_h[idx] = hn; }
}

// ---------------- host launcher ----------------
extern "C" void kernel_launch(void* const* d_in, const int* in_sizes, int n_in,
                              void* d_out, int out_size) {
    const float* img     = (const float*)d_in[0];
    const int*   toks    = (const int*)  d_in[1];
    const int*   lens    = (const int*)  d_in[2];
    const float* W_enc   = (const float*)d_in[3];
    const float* b_enc   = (const float*)d_in[4];
    const float* W_dec   = (const float*)d_in[5];
    const float* b_dec   = (const float*)d_in[6];
    const float* w_full  = (const float*)d_in[7];
    const float* b_full  = (const float*)d_in[8];
    const float* emb     = (const float*)d_in[9];
    const float* W_ih    = (const float*)d_in[10];
    const float* b_ih    = (const float*)d_in[11];
    const float* W_hh    = (const float*)d_in[12];
    const float* b_hh    = (const float*)d_in[13];
    const float* W_h0    = (const float*)d_in[14];
    const float* b_h0    = (const float*)d_in[15];
    const float* W_c0    = (const float*)d_in[16];
    const float* b_c0    = (const float*)d_in[17];
    const float* W_beta  = (const float*)d_in[18];
    const float* b_beta  = (const float*)d_in[19];
    const float* W_fc    = (const float*)d_in[20];
    const float* b_fc    = (const float*)d_in[21];
    float* out = (float*)d_out;

    // init
    k_sort<<<1, 64>>>(lens, toks, out);
    k_bcomb<<<8, 256>>>(b_ih, b_hh);
    k_mean<<<32, 256>>>(img);
    k_encatt<<<dim3(4, 49), 256>>>(img, W_enc, b_enc);

    // device symbol pointers (same address space; use symbols via small helper)
    float* p_mean;  cudaGetSymbolAddress((void**)&p_mean,  g_mean);
    float* p_h;     cudaGetSymbolAddress((void**)&p_h,     g_h);
    float* p_c;     cudaGetSymbolAddress((void**)&p_c,     g_c);
    float* p_hn;    cudaGetSymbolAddress((void**)&p_hn,    g_hn);
    float* p_dec;   cudaGetSymbolAddress((void**)&p_dec,   g_dec);
    float* p_awe;   cudaGetSymbolAddress((void**)&p_awe,   g_awe);
    float* p_x;     cudaGetSymbolAddress((void**)&p_x,     g_x);
    float* p_gates; cudaGetSymbolAddress((void**)&p_gates, g_gates);
    float* p_bcomb; cudaGetSymbolAddress((void**)&p_bcomb, g_bcomb);

    // h0 / c0
    k_gpart<<<dim3(4, 8), 256>>>(p_mean, W_h0, 512, 2048, 256, 0);
    k_reduce<<<(BSZ*512 + 255)/256, 256>>>(512, 8, b_h0, p_h, 512, 0, nullptr, 0);
    k_gpart<<<dim3(4, 8), 256>>>(p_mean, W_c0, 512, 2048, 256, 0);
    k_reduce<<<(BSZ*512 + 255)/256, 256>>>(512, 8, b_c0, p_c, 512, 0, nullptr, 0);

    for (int t = 0; t < TT; t++) {
        // dec_att = h @ W_dec^T + b_dec
        k_gpart<<<dim3(4, 16), 256>>>(p_h, W_dec, 512, 512, 32, 0);
        k_reduce<<<(BSZ*512 + 255)/256, 256>>>(512, 16, b_dec, p_dec, 512, 0, nullptr, 0);
        // attention scores/softmax (+ embedding copy into g_x)
        k_attn<<<32, 256>>>(emb, w_full, b_full, out, t);
        k_awe<<<256, 256>>>(img);
        // gate = sigmoid(h @ W_beta^T + b_beta); g_x[:,512:] = gate * awe
        k_gpart<<<dim3(16, 8), 256>>>(p_h, W_beta, 2048, 512, 64, 0);
        k_reduce<<<(BSZ*2048 + 255)/256, 256>>>(2048, 8, b_beta, p_x + 512, XKD, 2, p_awe, 0);
        // LSTM gates = x @ W_ih^T + h @ W_hh^T + (b_ih + b_hh)
        k_gpart<<<dim3(16, 8), 256>>>(p_x, W_ih, 2048, 2560, 320, 0);
        k_gpart<<<dim3(16, 8), 256>>>(p_h, W_hh, 2048, 512, 64, 8);
        k_reduce<<<(BSZ*2048 + 255)/256, 256>>>(2048, 16, p_bcomb, p_gates, 2048, 0, nullptr, 0);
        k_lstm<<<64, 256>>>(t);
        // preds = h_new @ W_fc^T + b_fc (masked)
        k_gpart<<<dim3(79, 2), 256>>>(p_hn, W_fc, 10000, 512, 256, 0);
        k_reduce<<<(BSZ*10000 + 255)/256, 256>>>(10000, 2, b_fc,
                                                 out + OFF_PRED + (long)t*VV,
                                                 (long)TT*VV, 3, nullptr, t);
    }
    (void)in_sizes; (void)n_in; (void)out_size;
}

// round 2
// speedup vs baseline: 1.0022x; 1.0022x over previous
#include <cuda_runtime.h>
#include <math.h>

// ---------------- problem constants ----------------
#define BSZ 32
#define PP 196          // 14*14 pixels
#define ENCD 2048
#define ATTD 512
#define DECD 512
#define EMBD 512
#define VV 10000
#define LL 52
#define TT 51           // decode steps
#define XKD 2560        // EMB + ENC (LSTM input width)

// output layout (floats), concat of (pred, toks, dlen, alphas, sort)
#define OFF_PRED  0L
#define OFF_TOKS  ((long)BSZ*TT*VV)                 // 16,320,000
#define OFF_DLEN  (OFF_TOKS + (long)BSZ*LL)         // +1664
#define OFF_ALPHA (OFF_DLEN + (long)BSZ)            // +32
#define OFF_SORT  (OFF_ALPHA + (long)BSZ*TT*PP)     // +319,872

// ---------------- device scratch (static, allocation-free) ----------------
__device__ float g_enc[BSZ*PP*ATTD];        // 12.8 MB: enc_att (sorted order)
__device__ float g_part[16L*BSZ*10016];     // split-K partials, up to 16 slices
__device__ float g_mean[BSZ*ENCD];
__device__ float g_h[BSZ*DECD];
__device__ float g_c[BSZ*DECD];
__device__ float g_hn[BSZ*DECD];
__device__ float g_dec[BSZ*ATTD];
__device__ float g_awe[BSZ*ENCD];
__device__ float g_x[BSZ*XKD];              // [emb(512) ; gated awe(2048)]
__device__ float g_gates[BSZ*2048];
__device__ float g_alpha[BSZ*PP];
__device__ float g_bcomb[2048];             // b_ih + b_hh
__device__ int   g_sort[BSZ];
__device__ int   g_dlen[BSZ];
__device__ int   g_toks[BSZ*LL];

__device__ __forceinline__ float sigm(float x) { return 1.f / (1.f + expf(-x)); }

// ---------------- sort (stable argsort descending) + gathers ----------------
__global__ void k_sort(const int* __restrict__ lens, const int* __restrict__ toks,
                       float* __restrict__ out) {
    int tid = threadIdx.x;
    if (tid < BSZ) {
        int li = lens[tid];
        int r = 0;
        for (int j = 0; j < BSZ; j++) {
            int lj = lens[j];
            if (lj > li || (lj == li && j < tid)) r++;
        }
        g_sort[r] = tid;
    }
    __syncthreads();
    if (tid < BSZ) {
        int si = g_sort[tid];
        int dl = lens[si] - 1;
        g_dlen[tid] = dl;
        out[OFF_DLEN + tid] = (float)dl;
        out[OFF_SORT + tid] = (float)si;
    }
    __syncthreads();
    for (int idx = tid; idx < BSZ*LL; idx += blockDim.x) {
        int b = idx / LL, l = idx - b*LL;
        int tk = toks[g_sort[b]*LL + l];
        g_toks[idx] = tk;
        out[OFF_TOKS + idx] = (float)tk;
    }
}

// ---------------- mean image feature (sorted) ----------------
__global__ void k_mean(const float* __restrict__ img) {
    int b = blockIdx.x;
    long base = (long)g_sort[b] * PP * ENCD;
    for (int e = threadIdx.x; e < ENCD; e += blockDim.x) {
        float s = 0.f;
        const float* p = img + base + e;
        #pragma unroll 4
        for (int pp = 0; pp < PP; pp++) s += p[(long)pp * ENCD];
        g_mean[b*ENCD + e] = s * (1.f / (float)PP);
    }
}

// ---------------- combined LSTM bias ----------------
__global__ void k_bcomb(const float* __restrict__ bih, const float* __restrict__ bhh) {
    int i = blockIdx.x * 256 + threadIdx.x;
    if (i < 2048) g_bcomb[i] = bih[i] + bhh[i];
}

// ---------------- enc_att = img_sorted @ W_enc^T + b_enc ----------------
// C[6272,512], K=2048.  BM=128, BN=128, BK=16, 256 threads, TM=TN=8.
__global__ void k_encatt(const float* __restrict__ img, const float* __restrict__ W,
                         const float* __restrict__ bias) {
    __shared__ float As[16*132];
    __shared__ float Bs[16*132];
    __shared__ long  rowbase[128];
    int tid = threadIdx.x;
    int bx = blockIdx.x;        // n tile (0..3)
    int by = blockIdx.y;        // m tile (0..48)

    if (tid < 128) {
        int rr = by*128 + tid;
        int b = rr / PP, p = rr - b*PP;
        rowbase[tid] = ((long)g_sort[b]*PP + p) * ENCD;
    }
    __syncthreads();

    float acc[8][8];
    #pragma unroll
    for (int i = 0; i < 8; i++)
        #pragma unroll
        for (int j = 0; j < 8; j++) acc[i][j] = 0.f;

    int tx = tid & 15, ty = tid >> 4;
    int m0 = ty*8, n0 = tx*8;

    for (int k0 = 0; k0 < ENCD; k0 += 16) {
        // stage A (128x16) and B (128x16)
        #pragma unroll
        for (int i = 0; i < 8; i++) {
            int idx = i*256 + tid;
            int k = idx & 15, r = idx >> 4;
            As[k*132 + r] = img[rowbase[r] + k0 + k];
            Bs[k*132 + r] = W[(long)(bx*128 + r)*ENCD + k0 + k];
        }
        __syncthreads();
        #pragma unroll 4
        for (int k = 0; k < 16; k++) {
            float a[8], bb[8];
            float4 a0 = *(const float4*)&As[k*132 + m0];
            float4 a1 = *(const float4*)&As[k*132 + m0 + 4];
            float4 b0 = *(const float4*)&Bs[k*132 + n0];
            float4 b1 = *(const float4*)&Bs[k*132 + n0 + 4];
            a[0]=a0.x;a[1]=a0.y;a[2]=a0.z;a[3]=a0.w;a[4]=a1.x;a[5]=a1.y;a[6]=a1.z;a[7]=a1.w;
            bb[0]=b0.x;bb[1]=b0.y;bb[2]=b0.z;bb[3]=b0.w;bb[4]=b1.x;bb[5]=b1.y;bb[6]=b1.z;bb[7]=b1.w;
            #pragma unroll
            for (int i = 0; i < 8; i++)
                #pragma unroll
                for (int j = 0; j < 8; j++)
                    acc[i][j] = fmaf(a[i], bb[j], acc[i][j]);
        }
        __syncthreads();
    }
    #pragma unroll
    for (int i = 0; i < 8; i++) {
        int row = by*128 + m0 + i;
        #pragma unroll
        for (int j = 0; j < 8; j++) {
            int col = bx*128 + n0 + j;
            g_enc[(long)row*ATTD + col] = acc[i][j] + bias[col];
        }
    }
}

// ---------------- skinny GEMM partial: part[s] = X[32,Kslice] @ W[N,Kslice]^T --------
// grid (ceil(N/128), SK), 256 threads, TM=4 TN=4.
__global__ void k_gpart(const float* __restrict__ X, const float* __restrict__ W,
                        int N, int K, int kslice, int s_off) {
    __shared__ float Xs[32*36];
    __shared__ float Ws[32*132];
    int tid = threadIdx.x;
    int nblk = blockIdx.x;
    int s = s_off + blockIdx.y;
    int k0 = blockIdx.y * kslice;

    float acc[4][4];
    #pragma unroll
    for (int i = 0; i < 4; i++)
        #pragma unroll
        for (int j = 0; j < 4; j++) acc[i][j] = 0.f;

    int m0 = (tid >> 5) * 4;      // 0..28
    int n0 = (tid & 31) * 4;      // 0..124

    for (int kk = 0; kk < kslice; kk += 32) {
        int kc = k0 + kk;
        // stage X chunk 32x32 transposed
        #pragma unroll
        for (int i = 0; i < 4; i++) {
            int idx = i*256 + tid;
            int k = idx & 31, m = idx >> 5;
            Xs[k*36 + m] = X[(long)m*K + kc + k];
        }
        // stage W chunk 128x32 transposed
        #pragma unroll
        for (int i = 0; i < 16; i++) {
            int idx = i*256 + tid;
            int k = idx & 31, n = idx >> 5;
            int ng = nblk*128 + n;
            Ws[k*132 + n] = (ng < N) ? W[(long)ng*K + kc + k] : 0.f;
        }
        __syncthreads();
        #pragma unroll 8
        for (int k = 0; k < 32; k++) {
            float4 xa = *(const float4*)&Xs[k*36 + m0];
            float4 wb = *(const float4*)&Ws[k*132 + n0];
            float xv[4] = {xa.x, xa.y, xa.z, xa.w};
            float wv[4] = {wb.x, wb.y, wb.z, wb.w};
            #pragma unroll
            for (int i = 0; i < 4; i++)
                #pragma unroll
                for (int j = 0; j < 4; j++)
                    acc[i][j] = fmaf(xv[i], wv[j], acc[i][j]);
        }
        __syncthreads();
    }
    #pragma unroll
    for (int i = 0; i < 4; i++) {
        int m = m0 + i;
        #pragma unroll
        for (int j = 0; j < 4; j++) {
            int ng = nblk*128 + n0 + j;
            if (ng < N) g_part[((long)s*BSZ + m)*N + ng] = acc[i][j];
        }
    }
}

// ---------------- reduce partials + epilogue ----------------
// mode 0: out[m*ostride+n] = sum + bias[n]
// mode 2: out[m*ostride+n] = aux[m*N+n] * sigmoid(sum + bias[n])    (beta gate)
// mode 3: out[m*ostride+n] = (t < dlen[m]) ? sum + bias[n] : 0      (FC preds)
__global__ void k_reduce(int N, int S, const float* __restrict__ bias,
                         float* __restrict__ out, long ostride, int mode,
                         const float* __restrict__ aux, int t) {
    int idx = blockIdx.x*256 + threadIdx.x;
    if (idx >= BSZ*N) return;
    int m = idx / N, n = idx - m*N;
    const float* p = g_part + (long)m*N + n;
    float s = 0.f;
    for (int si = 0; si < S; si++) s += p[(long)si*BSZ*N];
    s += bias[n];
    if (mode == 0) {
        out[(long)m*ostride + n] = s;
    } else if (mode == 2) {
        out[(long)m*ostride + n] = aux[m*N + n] * sigm(s);
    } else {
        out[(long)m*ostride + n] = (t < g_dlen[m]) ? s : 0.f;
    }
}

// ---------------- attention: scores + softmax + alpha out + emb copy ----------------
__global__ void k_attn(const float* __restrict__ emb_table, const float* __restrict__ w_full,
                       const float* __restrict__ b_full, float* __restrict__ out, int t) {
    __shared__ float dec_s[ATTD];
    __shared__ float wf[ATTD];
    __shared__ float sc[PP];
    __shared__ float red[256];
    int b = blockIdx.x;
    int tid = threadIdx.x;
    bool act = (t < g_dlen[b]);

    // copy embedding of current token into LSTM input buffer
    int tok = g_toks[b*LL + t];
    for (int e = tid; e < EMBD; e += 256)
        g_x[(long)b*XKD + e] = emb_table[(long)tok*EMBD + e];
    for (int a = tid; a < ATTD; a += 256) {
        dec_s[a] = g_dec[b*ATTD + a];
        wf[a] = w_full[a];
    }
    __syncthreads();

    // scores over 196 pixels
    int wid = tid >> 5, lane = tid & 31;
    float bf = b_full[0];
    for (int p = wid; p < PP; p += 8) {
        const float* er = g_enc + ((long)b*PP + p)*ATTD;
        float s = 0.f;
        #pragma unroll 4
        for (int a = lane; a < ATTD; a += 32) {
            float v = er[a] + dec_s[a];
            s = fmaf(fmaxf(v, 0.f), wf[a], s);
        }
        #pragma unroll
        for (int off = 16; off > 0; off >>= 1)
            s += __shfl_xor_sync(0xffffffffu, s, off);
        if (lane == 0) sc[p] = s + bf;
    }
    __syncthreads();

    // softmax over PP
    float v = (tid < PP) ? sc[tid] : -3.0e38f;
    red[tid] = v; __syncthreads();
    for (int s2 = 128; s2 > 0; s2 >>= 1) {
        if (tid < s2) red[tid] = fmaxf(red[tid], red[tid + s2]);
        __syncthreads();
    }
    float mx = red[0];
    __syncthreads();
    float ev = (tid < PP) ? expf(sc[tid] - mx) : 0.f;
    red[tid] = ev; __syncthreads();
    for (int s2 = 128; s2 > 0; s2 >>= 1) {
        if (tid < s2) red[tid] += red[tid + s2];
        __syncthreads();
    }
    float inv = 1.f / red[0];
    if (tid < PP) {
        float al = ev * inv;
        g_alpha[b*PP + tid] = al;
        out[OFF_ALPHA + ((long)b*TT + t)*PP + tid] = act ? al : 0.f;
    }
}

// ---------------- awe = alpha @ img_sorted  (grid 32 b x 8 e-chunks) ----------------
__global__ void k_awe(const float* __restrict__ img) {
    __shared__ float al[PP];
    int b = blockIdx.x >> 3;
    int ch = blockIdx.x & 7;
    int tid = threadIdx.x;
    if (tid < PP) al[tid] = g_alpha[b*PP + tid];
    __syncthreads();
    int e = ch*256 + tid;
    const float* base = img + ((long)g_sort[b]*PP)*ENCD + e;
    float s = 0.f;
    #pragma unroll 4
    for (int p = 0; p < PP; p++) s = fmaf(al[p], base[(long)p*ENCD], s);
    g_awe[b*ENCD + e] = s;
}

// ---------------- LSTM pointwise update ----------------
__global__ void k_lstm(int t) {
    int idx = blockIdx.x*256 + threadIdx.x;
    if (idx >= BSZ*DECD) return;
    int m = idx / DECD, j = idx - m*DECD;
    const float* g = g_gates + m*2048;
    float gi = g[j], gf = g[j + 512], gg = g[j + 1024], go = g[j + 1536];
    float c = g_c[idx];
    float cn = sigm(gf)*c + sigm(gi)*tanhf(gg);
    float hn = sigm(go)*tanhf(cn);
    g_hn[idx] = hn;
    if (t < g_dlen[m]) { g_c[idx] = cn; g_h[idx] = hn; }
}

// ---------------- host launcher ----------------
extern "C" void kernel_launch(void* const* d_in, const int* in_sizes, int n_in,
                              void* d_out, int out_size) {
    const float* img     = (const float*)d_in[0];
    const int*   toks    = (const int*)  d_in[1];
    const int*   lens    = (const int*)  d_in[2];
    const float* W_enc   = (const float*)d_in[3];
    const float* b_enc   = (const float*)d_in[4];
    const float* W_dec   = (const float*)d_in[5];
    const float* b_dec   = (const float*)d_in[6];
    const float* w_full  = (const float*)d_in[7];
    const float* b_full  = (const float*)d_in[8];
    const float* emb     = (const float*)d_in[9];
    const float* W_ih    = (const float*)d_in[10];
    const float* b_ih    = (const float*)d_in[11];
    const float* W_hh    = (const float*)d_in[12];
    const float* b_hh    = (const float*)d_in[13];
    const float* W_h0    = (const float*)d_in[14];
    const float* b_h0    = (const float*)d_in[15];
    const float* W_c0    = (const float*)d_in[16];
    const float* b_c0    = (const float*)d_in[17];
    const float* W_beta  = (const float*)d_in[18];
    const float* b_beta  = (const float*)d_in[19];
    const float* W_fc    = (const float*)d_in[20];
    const float* b_fc    = (const float*)d_in[21];
    float* out = (float*)d_out;

    // init
    k_sort<<<1, 64>>>(lens, toks, out);
    k_bcomb<<<8, 256>>>(b_ih, b_hh);
    k_mean<<<32, 256>>>(img);
    k_encatt<<<dim3(4, 49), 256>>>(img, W_enc, b_enc);

    // device symbol pointers (same address space; use symbols via small helper)
    float* p_mean;  cudaGetSymbolAddress((void**)&p_mean,  g_mean);
    float* p_h;     cudaGetSymbolAddress((void**)&p_h,     g_h);
    float* p_c;     cudaGetSymbolAddress((void**)&p_c,     g_c);
    float* p_hn;    cudaGetSymbolAddress((void**)&p_hn,    g_hn);
    float* p_dec;   cudaGetSymbolAddress((void**)&p_dec,   g_dec);
    float* p_awe;   cudaGetSymbolAddress((void**)&p_awe,   g_awe);
    float* p_x;     cudaGetSymbolAddress((void**)&p_x,     g_x);
    float* p_gates; cudaGetSymbolAddress((void**)&p_gates, g_gates);
    float* p_bcomb; cudaGetSymbolAddress((void**)&p_bcomb, g_bcomb);

    // h0 / c0
    k_gpart<<<dim3(4, 8), 256>>>(p_mean, W_h0, 512, 2048, 256, 0);
    k_reduce<<<(BSZ*512 + 255)/256, 256>>>(512, 8, b_h0, p_h, 512, 0, nullptr, 0);
    k_gpart<<<dim3(4, 8), 256>>>(p_mean, W_c0, 512, 2048, 256, 0);
    k_reduce<<<(BSZ*512 + 255)/256, 256>>>(512, 8, b_c0, p_c, 512, 0, nullptr, 0);

    for (int t = 0; t < TT; t++) {
        // dec_att = h @ W_dec^T + b_dec
        k_gpart<<<dim3(4, 16), 256>>>(p_h, W_dec, 512, 512, 32, 0);
        k_reduce<<<(BSZ*512 + 255)/256, 256>>>(512, 16, b_dec, p_dec, 512, 0, nullptr, 0);
        // attention scores/softmax (+ embedding copy into g_x)
        k_attn<<<32, 256>>>(emb, w_full, b_full, out, t);
        k_awe<<<256, 256>>>(img);
        // gate = sigmoid(h @ W_beta^T + b_beta); g_x[:,512:] = gate * awe
        k_gpart<<<dim3(16, 8), 256>>>(p_h, W_beta, 2048, 512, 64, 0);
        k_reduce<<<(BSZ*2048 + 255)/256, 256>>>(2048, 8, b_beta, p_x + 512, XKD, 2, p_awe, 0);
        // LSTM gates = x @ W_ih^T + h @ W_hh^T + (b_ih + b_hh)
        k_gpart<<<dim3(16, 8), 256>>>(p_x, W_ih, 2048, 2560, 320, 0);
        k_gpart<<<dim3(16, 8), 256>>>(p_h, W_hh, 2048, 512, 64, 8);
        k_reduce<<<(BSZ*2048 + 255)/256, 256>>>(2048, 16, p_bcomb, p_gates, 2048, 0, nullptr, 0);
        k_lstm<<<64, 256>>>(t);
        // preds = h_new @ W_fc^T + b_fc (masked)
        k_gpart<<<dim3(79, 2), 256>>>(p_hn, W_fc, 10000, 512, 256, 0);
        k_reduce<<<(BSZ*10000 + 255)/256, 256>>>(10000, 2, b_fc,
                                                 out + OFF_PRED + (long)t*VV,
                                                 (long)TT*VV, 3, nullptr, t);
    }
    (void)in_sizes; (void)n_in; (void)out_size;
}

// round 3
// speedup vs baseline: 1.5468x; 1.5434x over previous
#include <cuda_runtime.h>
#include <math.h>

#define BSZ 32
#define PP 196
#define ENCD 2048
#define ATTD 512
#define DECD 512
#define VV 10000
#define LL 52
#define TT 51
#define GRID 148

#define OFF_PRED  0L
#define OFF_TOKS  ((long)BSZ*TT*VV)
#define OFF_DLEN  (OFF_TOKS + (long)BSZ*LL)
#define OFF_ALPHA (OFF_DLEN + (long)BSZ)
#define OFF_SORT  (OFF_ALPHA + (long)BSZ*TT*PP)

// ---------------- static device scratch ----------------
__device__ float g_enc[6272L*512];
__device__ float g_embg[51L*32*2048];
__device__ float g_pDec[8*32*512];
__device__ float g_pHH[2*32*2048];
__device__ float g_pBeta[2*32*2048];
__device__ float g_pIH[8*32*2048];        // also reused for h0/c0 partials [16][32][512]
__device__ float g_pFC[2L*32*10240];
__device__ float g_mean[32*2048];
__device__ float g_h[32*512];
__device__ float g_c[32*512];
__device__ float g_hn[32*512];
__device__ float g_gates[32*2048];
__device__ float g_x2[32*2048];
__device__ float g_alpha[32*196];
__device__ float g_bcomb[2048];
__device__ int   g_sort[32];
__device__ int   g_dlen[32];
__device__ int   g_toks[32*LL];
__device__ unsigned g_barcnt;
__device__ volatile unsigned g_bargen;

__device__ __forceinline__ float sigm(float x) { return 1.f / (1.f + expf(-x)); }

// ---------------- grid-wide software barrier ----------------
__device__ __forceinline__ void gridbar() {
    __syncthreads();
    if (threadIdx.x == 0) {
        __threadfence();
        unsigned gen = g_bargen;
        if (atomicAdd(&g_barcnt, 1u) == GRID - 1) {
            g_barcnt = 0;
            __threadfence();
            g_bargen = gen + 1;
        } else {
            while (g_bargen == gen) { }
        }
        __threadfence();
    }
    __syncthreads();
}

// ---------------- generic 32-row GEMM partial tile ----------------
// part[m][nbase+n] = sum_{k in [k0,k0+klen)} X[row(m)][k] * W[nbase+n][wcol0+k]
template<int NT>
__device__ void gemm32(const float* __restrict__ X, int ldx,
                       const int* __restrict__ gidx, int gstride,
                       const float* __restrict__ W, int ldw, int wcol0,
                       int Nfull, int nbase, int k0, int klen,
                       float* __restrict__ part, int Nld, float* pool)
{
    const int TN = NT / 32;
    float* Xs = pool;                         // 32k x 36 (k-major)
    float* Ws = pool + 1184;                  // 32k x (NT+8)
    int* roff = (int*)(pool + 1184 + 32*(NT+8));
    const int tid = threadIdx.x;
    __syncthreads();
    if (tid < 32) roff[tid] = (gidx ? gidx[tid * gstride] : tid) * ldx;
    __syncthreads();

    float acc[4][TN];
    #pragma unroll
    for (int i = 0; i < 4; i++)
        #pragma unroll
        for (int j = 0; j < TN; j++) acc[i][j] = 0.f;

    const int m0 = (tid >> 5) * 4;
    const int n0 = (tid & 31) * TN;
    const int xm = tid >> 3, xk = (tid & 7) * 4;

    for (int kk = 0; kk < klen; kk += 32) {
        const int kc = k0 + kk;
        {
            float4 v = *(const float4*)(X + roff[xm] + kc + xk);
            Xs[(xk+0)*36 + xm] = v.x; Xs[(xk+1)*36 + xm] = v.y;
            Xs[(xk+2)*36 + xm] = v.z; Xs[(xk+3)*36 + xm] = v.w;
        }
        #pragma unroll
        for (int j = 0; j < TN; j++) {
            int id = j*256 + tid;
            int n = id >> 3, k4 = (id & 7) * 4;
            int ng = nbase + n;
            float4 v = make_float4(0.f, 0.f, 0.f, 0.f);
            if (ng < Nfull) v = *(const float4*)(W + (long)ng*ldw + wcol0 + kc + k4);
            Ws[(k4+0)*(NT+8) + n] = v.x; Ws[(k4+1)*(NT+8) + n] = v.y;
            Ws[(k4+2)*(NT+8) + n] = v.z; Ws[(k4+3)*(NT+8) + n] = v.w;
        }
        __syncthreads();
        #pragma unroll
        for (int k = 0; k < 32; k++) {
            float4 a = *(const float4*)&Xs[k*36 + m0];
            float av[4] = {a.x, a.y, a.z, a.w};
            float wv[TN];
            #pragma unroll
            for (int j = 0; j < TN; j += 4) {
                float4 w4 = *(const float4*)&Ws[k*(NT+8) + n0 + j];
                wv[j] = w4.x; wv[j+1] = w4.y; wv[j+2] = w4.z; wv[j+3] = w4.w;
            }
            #pragma unroll
            for (int i = 0; i < 4; i++)
                #pragma unroll
                for (int j = 0; j < TN; j++)
                    acc[i][j] = fmaf(av[i], wv[j], acc[i][j]);
        }
        __syncthreads();
    }
    #pragma unroll
    for (int i = 0; i < 4; i++)
        #pragma unroll
        for (int j = 0; j < TN; j++)
            part[(long)(m0+i)*Nld + nbase + n0 + j] = acc[i][j];
}

// ---------------- encoder tile: 128 rows x 64 cols, K=2048 ----------------
__device__ void enc_task(int tm, int tn, const float* __restrict__ img,
                         const float* __restrict__ W_enc, const float* __restrict__ b_enc,
                         float* pool)
{
    float* As = pool;              // 32k x 132
    float* Bs = pool + 4224;       // 32k x 68
    int* rowb = (int*)(pool + 6400);
    const int tid = threadIdx.x;
    __syncthreads();
    if (tid < 128) {
        int rr = tm*128 + tid;
        int b = rr / PP, p = rr - b*PP;
        rowb[tid] = (g_sort[b]*PP + p) * ENCD;
    }
    __syncthreads();
    float acc[8][4];
    #pragma unroll
    for (int i = 0; i < 8; i++)
        #pragma unroll
        for (int j = 0; j < 4; j++) acc[i][j] = 0.f;
    const int ty = tid >> 4, tx = tid & 15;
    const int m0 = ty*8, n0 = tx*4;
    for (int kc = 0; kc < ENCD; kc += 32) {
        #pragma unroll
        for (int j = 0; j < 4; j++) {
            int id = j*256 + tid;
            int m = id >> 3, k4 = (id & 7) * 4;
            float4 v = *(const float4*)(img + rowb[m] + kc + k4);
            As[(k4+0)*132+m] = v.x; As[(k4+1)*132+m] = v.y;
            As[(k4+2)*132+m] = v.z; As[(k4+3)*132+m] = v.w;
        }
        #pragma unroll
        for (int j = 0; j < 2; j++) {
            int id = j*256 + tid;
            int n = id >> 3, k4 = (id & 7) * 4;
            float4 v = *(const float4*)(W_enc + (long)(tn*64+n)*ENCD + kc + k4);
            Bs[(k4+0)*68+n] = v.x; Bs[(k4+1)*68+n] = v.y;
            Bs[(k4+2)*68+n] = v.z; Bs[(k4+3)*68+n] = v.w;
        }
        __syncthreads();
        #pragma unroll
        for (int k = 0; k < 32; k++) {
            float4 a0 = *(const float4*)&As[k*132 + m0];
            float4 a1 = *(const float4*)&As[k*132 + m0 + 4];
            float4 b0 = *(const float4*)&Bs[k*68 + n0];
            float av[8] = {a0.x,a0.y,a0.z,a0.w,a1.x,a1.y,a1.z,a1.w};
            float bv[4] = {b0.x,b0.y,b0.z,b0.w};
            #pragma unroll
            for (int i = 0; i < 8; i++)
                #pragma unroll
                for (int j = 0; j < 4; j++)
                    acc[i][j] = fmaf(av[i], bv[j], acc[i][j]);
        }
        __syncthreads();
    }
    #pragma unroll
    for (int i = 0; i < 8; i++) {
        int row = tm*128 + m0 + i;
        #pragma unroll
        for (int j = 0; j < 4; j++) {
            int col = tn*64 + n0 + j;
            g_enc[(long)row*512 + col] = acc[i][j] + b_enc[col];
        }
    }
}

// ---------------- attention scores + softmax ----------------
__device__ void attn_task(int b, int t, const float* __restrict__ b_dec,
                          const float* __restrict__ w_full, const float* __restrict__ b_full,
                          float* __restrict__ out, float* pool)
{
    float* dec_s = pool;
    float* wf    = pool + 512;
    float* sc    = pool + 1024;
    float* red   = pool + 1280;
    const int tid = threadIdx.x;
    __syncthreads();
    for (int a = tid; a < ATTD; a += 256) {
        float s = b_dec[a];
        #pragma unroll
        for (int s8 = 0; s8 < 8; s8++) s += g_pDec[s8*16384 + b*512 + a];
        dec_s[a] = s;
        wf[a] = w_full[a];
    }
    __syncthreads();
    int wid = tid >> 5, lane = tid & 31;
    float bf = b_full[0];
    for (int p = wid; p < PP; p += 8) {
        const float* er = g_enc + ((long)b*PP + p)*ATTD;
        float s = 0.f;
        #pragma unroll 4
        for (int a = lane; a < ATTD; a += 32) {
            float v = er[a] + dec_s[a];
            s = fmaf(fmaxf(v, 0.f), wf[a], s);
        }
        #pragma unroll
        for (int off = 16; off > 0; off >>= 1) s += __shfl_xor_sync(0xffffffffu, s, off);
        if (lane == 0) sc[p] = s + bf;
    }
    __syncthreads();
    float v = (tid < PP) ? sc[tid] : -3.0e38f;
    red[tid] = v; __syncthreads();
    for (int s2 = 128; s2 > 0; s2 >>= 1) {
        if (tid < s2) red[tid] = fmaxf(red[tid], red[tid + s2]);
        __syncthreads();
    }
    float mx = red[0];
    __syncthreads();
    float ev = (tid < PP) ? expf(sc[tid] - mx) : 0.f;
    red[tid] = ev; __syncthreads();
    for (int s2 = 128; s2 > 0; s2 >>= 1) {
        if (tid < s2) red[tid] += red[tid + s2];
        __syncthreads();
    }
    float inv = 1.f / red[0];
    if (tid < PP) {
        float al = ev * inv;
        g_alpha[b*PP + tid] = al;
        out[OFF_ALPHA + ((long)b*TT + t)*PP + tid] = (t < g_dlen[b]) ? al : 0.f;
    }
}

// ---------------- awe + beta gate -> x2 ----------------
__device__ void awe_task(int b, int ch, const float* __restrict__ img,
                         const float* __restrict__ b_beta, float* pool)
{
    float* al = pool;
    const int tid = threadIdx.x;
    __syncthreads();
    if (tid < PP) al[tid] = g_alpha[b*PP + tid];
    __syncthreads();
    int e = ch*256 + tid;
    long base = (long)(g_sort[b]*PP) * ENCD + e;
    float s = 0.f;
    #pragma unroll 7
    for (int p = 0; p < PP; p++) s = fmaf(al[p], img[base + (long)p*ENCD], s);
    float bsum = g_pBeta[b*2048 + e] + g_pBeta[65536 + b*2048 + e] + b_beta[e];
    g_x2[b*2048 + e] = s * sigm(bsum);
}

// ---------------- main persistent kernel ----------------
__global__ void __launch_bounds__(256, 1)
persist(const float* __restrict__ img, const int* __restrict__ toks, const int* __restrict__ lens,
        const float* __restrict__ W_enc, const float* __restrict__ b_enc,
        const float* __restrict__ W_dec, const float* __restrict__ b_dec,
        const float* __restrict__ w_full, const float* __restrict__ b_full,
        const float* __restrict__ emb,
        const float* __restrict__ W_ih, const float* __restrict__ b_ih,
        const float* __restrict__ W_hh, const float* __restrict__ b_hh,
        const float* __restrict__ W_h0, const float* __restrict__ b_h0,
        const float* __restrict__ W_c0, const float* __restrict__ b_c0,
        const float* __restrict__ W_beta, const float* __restrict__ b_beta,
        const float* __restrict__ W_fc, const float* __restrict__ b_fc,
        float* __restrict__ out)
{
    __shared__ float pool[9700];
    const int bid = blockIdx.x;
    const int tid = threadIdx.x;

    // ---- P0: sort + token gather + combined bias ----
    if (bid == 0) {
        if (tid < BSZ) {
            int li = lens[tid];
            int r = 0;
            for (int j = 0; j < BSZ; j++) {
                int lj = lens[j];
                if (lj > li || (lj == li && j < tid)) r++;
            }
            g_sort[r] = tid;
        }
        __syncthreads();
        if (tid < BSZ) {
            int si = g_sort[tid];
            int dl = lens[si] - 1;
            g_dlen[tid] = dl;
            out[OFF_DLEN + tid] = (float)dl;
            out[OFF_SORT + tid] = (float)si;
        }
        __syncthreads();
        for (int idx = tid; idx < BSZ*LL; idx += 256) {
            int b = idx / LL, l = idx - b*LL;
            int tk = toks[g_sort[b]*LL + l];
            g_toks[idx] = tk;
            out[OFF_TOKS + idx] = (float)tk;
        }
    } else if (bid == 1) {
        for (int i = tid; i < 2048; i += 256) g_bcomb[i] = b_ih[i] + b_hh[i];
    }
    gridbar();

    // ---- P1: enc_att (392) | embg precompute (408) | mean (32) ----
    for (int task = bid; task < 832; task += GRID) {
        if (task < 392) {
            enc_task(task >> 3, task & 7, img, W_enc, b_enc, pool);
        } else if (task < 800) {
            int id = task - 392;
            int tt = id >> 3, nt = id & 7;
            gemm32<256>(emb, 512, g_toks + tt, LL, W_ih, 2560, 0,
                        2048, nt*256, 0, 512, g_embg + (long)tt*65536, 2048, pool);
        } else {
            int b = task - 800;
            __syncthreads();
            long srow = (long)g_sort[b] * PP * ENCD;
            int e0 = tid * 8;
            float a[8] = {0,0,0,0,0,0,0,0};
            #pragma unroll 4
            for (int p = 0; p < PP; p++) {
                const float* r = img + srow + (long)p*ENCD + e0;
                float4 v0 = *(const float4*)r;
                float4 v1 = *(const float4*)(r + 4);
                a[0]+=v0.x; a[1]+=v0.y; a[2]+=v0.z; a[3]+=v0.w;
                a[4]+=v1.x; a[5]+=v1.y; a[6]+=v1.z; a[7]+=v1.w;
            }
            #pragma unroll
            for (int i = 0; i < 8; i++)
                g_mean[b*2048 + e0 + i] = a[i] * (1.f/196.f);
        }
    }
    gridbar();

    // ---- P2: h0/c0 partials (32 tasks) ----
    for (int task = bid; task < 32; task += GRID) {
        int half = task >> 4, nt = (task >> 3) & 1, sk = task & 7;
        gemm32<256>(g_mean, 2048, (const int*)0, 0, half ? W_c0 : W_h0, 2048, 0,
                    512, nt*256, sk*256, 256, g_pIH + (half*8 + sk)*16384, 512, pool);
    }
    gridbar();

    // ---- P3: reduce h0/c0 ----
    for (int task = bid; task < 32; task += GRID) {
        int b = task;
        for (int j = tid; j < 512; j += 256) {
            float s = b_h0[j], s2 = b_c0[j];
            #pragma unroll
            for (int s8 = 0; s8 < 8; s8++) {
                s  += g_pIH[s8*16384 + b*512 + j];
                s2 += g_pIH[(8+s8)*16384 + b*512 + j];
            }
            g_h[b*512 + j] = s;
            g_c[b*512 + j] = s2;
        }
    }
    gridbar();

    // ---- decode loop ----
    for (int t = 0; t < TT; t++) {
        // phase1: dec(16) | hh(16) | beta(16) | FC(t-1)(80)
        int n1 = (t > 0) ? 128 : 48;
        for (int task = bid; task < n1; task += GRID) {
            if (task < 16) {
                int nt = (task >> 3) & 1, sk = task & 7;
                gemm32<256>(g_h, 512, (const int*)0, 0, W_dec, 512, 0,
                            512, nt*256, sk*64, 64, g_pDec + sk*16384, 512, pool);
            } else if (task < 32) {
                int rid = task - 16, nt = rid >> 1, sk = rid & 1;
                gemm32<256>(g_h, 512, (const int*)0, 0, W_hh, 512, 0,
                            2048, nt*256, sk*256, 256, g_pHH + sk*65536, 2048, pool);
            } else if (task < 48) {
                int rid = task - 32, nt = rid >> 1, sk = rid & 1;
                gemm32<256>(g_h, 512, (const int*)0, 0, W_beta, 512, 0,
                            2048, nt*256, sk*256, 256, g_pBeta + sk*65536, 2048, pool);
            } else {
                int rid = task - 48, nt = rid >> 1, sk = rid & 1;
                gemm32<256>(g_hn, 512, (const int*)0, 0, W_fc, 512, 0,
                            10000, nt*256, sk*256, 256, g_pFC + (long)sk*327680, 10240, pool);
            }
        }
        gridbar();

        // phase2: attn(32) | FC(t-1) reduce+write(160)
        int n2 = (t > 0) ? 192 : 32;
        for (int task = bid; task < n2; task += GRID) {
            if (task < 32) {
                attn_task(task, t, b_dec, w_full, b_full, out, pool);
            } else {
                int rid = task - 32;
                int b = rid / 5, ch = rid % 5;
                int tp = t - 1;
                bool act = tp < g_dlen[b];
                int n0 = ch * 2000;
                for (int n = n0 + tid; n < n0 + 2000; n += 256) {
                    float s = g_pFC[(long)b*10240 + n] + g_pFC[327680L + (long)b*10240 + n] + b_fc[n];
                    out[OFF_PRED + ((long)b*TT + tp)*VV + n] = act ? s : 0.f;
                }
            }
        }
        gridbar();

        // phase3: awe+gate->x2 (256) | gates base (32)
        for (int task = bid; task < 288; task += GRID) {
            if (task < 256) {
                awe_task(task >> 3, task & 7, img, b_beta, pool);
            } else {
                int b = task - 256;
                for (int j = tid; j < 2048; j += 256)
                    g_gates[b*2048 + j] = g_pHH[b*2048 + j] + g_pHH[65536 + b*2048 + j]
                                        + g_embg[(long)t*65536 + b*2048 + j] + g_bcomb[j];
            }
        }
        gridbar();

        // phase4: x2 @ W_ih[:,512:]^T (128 tasks)
        for (int task = bid; task < 128; task += GRID) {
            int nt = task >> 3, sk = task & 7;
            gemm32<128>(g_x2, 2048, (const int*)0, 0, W_ih, 2560, 512,
                        2048, nt*128, sk*256, 256, g_pIH + sk*65536, 2048, pool);
        }
        gridbar();

        // phase5: gate reduce + LSTM pointwise (32 tasks)
        for (int task = bid; task < 32; task += GRID) {
            int b = task;
            for (int j = tid; j < 512; j += 256) {
                float gi = g_gates[b*2048 + j];
                float gf = g_gates[b*2048 + j + 512];
                float gg = g_gates[b*2048 + j + 1024];
                float go = g_gates[b*2048 + j + 1536];
                #pragma unroll
                for (int s8 = 0; s8 < 8; s8++) {
                    const float* p = g_pIH + s8*65536 + b*2048;
                    gi += p[j]; gf += p[j + 512]; gg += p[j + 1024]; go += p[j + 1536];
                }
                float c = g_c[b*512 + j];
                float cn = sigm(gf)*c + sigm(gi)*tanhf(gg);
                float hn = sigm(go)*tanhf(cn);
                g_hn[b*512 + j] = hn;
                if (t < g_dlen[b]) { g_c[b*512 + j] = cn; g_h[b*512 + j] = hn; }
            }
        }
        gridbar();
    }

    // ---- final FC for t = TT-1 ----
    for (int task = bid; task < 80; task += GRID) {
        int nt = task >> 1, sk = task & 1;
        gemm32<256>(g_hn, 512, (const int*)0, 0, W_fc, 512, 0,
                    10000, nt*256, sk*256, 256, g_pFC + (long)sk*327680, 10240, pool);
    }
    gridbar();
    for (int task = bid; task < 160; task += GRID) {
        int b = task / 5, ch = task % 5;
        int tp = TT - 1;
        bool act = tp < g_dlen[b];
        int n0 = ch * 2000;
        for (int n = n0 + tid; n < n0 + 2000; n += 256) {
            float s = g_pFC[(long)b*10240 + n] + g_pFC[327680L + (long)b*10240 + n] + b_fc[n];
            out[OFF_PRED + ((long)b*TT + tp)*VV + n] = act ? s : 0.f;
        }
    }
}

// ---------------- host launcher ----------------
extern "C" void kernel_launch(void* const* d_in, const int* in_sizes, int n_in,
                              void* d_out, int out_size) {
    persist<<<GRID, 256>>>(
        (const float*)d_in[0],  (const int*)d_in[1],   (const int*)d_in[2],
        (const float*)d_in[3],  (const float*)d_in[4],
        (const float*)d_in[5],  (const float*)d_in[6],
        (const float*)d_in[7],  (const float*)d_in[8],
        (const float*)d_in[9],
        (const float*)d_in[10], (const float*)d_in[11],
        (const float*)d_in[12], (const float*)d_in[13],
        (const float*)d_in[14], (const float*)d_in[15],
        (const float*)d_in[16], (const float*)d_in[17],
        (const float*)d_in[18], (const float*)d_in[19],
        (const float*)d_in[20], (const float*)d_in[21],
        (float*)d_out);
    (void)in_sizes; (void)n_in; (void)out_size;
}